// round 12
// baseline (speedup 1.0000x reference)
#include <cuda_runtime.h>
#include <cuda_bf16.h>
#include <cuda_fp16.h>
#include <math_constants.h>
#include <mma.h>

using namespace nvcuda;

#define BB 2
#define NN 2048
#define HH 8
#define DD 64
#define FIN 512
#define HD 512
#define EPS 1e-5f
#define SCALE 0.125f
#define L2E8 0.18033688011112042f   // log2(e)/8
#define NW (NN / 32)

// Device scratch
__device__ __half g_hh[BB * NN * HD];                  // projected features fp16 row-major
__device__ __half g_hhT[BB * HH * DD * NN];            // [b][h][d][n] fp16 (for V-phase)
__device__ __half g_S[(size_t)BB * HH * NN * NN];      // scaled exp values fp16
__device__ float g_O[BB * NN * HD];
__device__ float g_rowsum[BB * HH * NN];
__device__ unsigned g_mask[(size_t)BB * NN * NW];

__device__ __forceinline__ float f2tf32(float x) {
    float r;
    asm("cvt.rna.tf32.f32 %0, %1;" : "=f"(r) : "f"(x));
    return r;
}

__device__ __forceinline__ void mma_f16(float d[4], unsigned a0, unsigned a1,
                                        unsigned a2, unsigned a3,
                                        unsigned b0, unsigned b1) {
    asm volatile(
        "mma.sync.aligned.m16n8k16.row.col.f32.f16.f16.f32 "
        "{%0,%1,%2,%3}, {%4,%5,%6,%7}, {%8,%9}, {%0,%1,%2,%3};"
        : "+f"(d[0]), "+f"(d[1]), "+f"(d[2]), "+f"(d[3])
        : "r"(a0), "r"(a1), "r"(a2), "r"(a3), "r"(b0), "r"(b1));
}

// ---------------------------------------------------------------------------
// K0: pack adj -> bitmask
// ---------------------------------------------------------------------------
__global__ void k_pack(const int* __restrict__ adj) {
    const int row = blockIdx.x;
    const int t = threadIdx.x;
    const int warp = t >> 5, lane = t & 31;
    const int* arow = adj + (size_t)row * NN;
    #pragma unroll
    for (int j = warp; j < NW; j += 8) {
        unsigned bit = (arow[j * 32 + lane] != 0) ? 1u : 0u;
        unsigned word = __ballot_sync(0xffffffffu, bit);
        if (lane == 0) g_mask[(size_t)row * NW + j] = word;
    }
}

// ---------------------------------------------------------------------------
// K1: h = x @ W + b (tf32 wmma); writes fp16 g_hh + transposed g_hhT
// ---------------------------------------------------------------------------
__global__ void k_proj(const float* __restrict__ x, const float* __restrict__ W,
                       const float* __restrict__ bias) {
    __shared__ float Xs[64][72];
    __shared__ float Ws[64][72];

    const int t = threadIdx.x;
    const int wid = t >> 5;
    const int warp_m = (wid & 1) * 32;
    const int warp_n = (wid >> 1) * 32;
    const int row0 = blockIdx.y * 64;
    const int col0 = blockIdx.x * 64;

    wmma::fragment<wmma::accumulator, 16, 16, 8, float> c[2][2];
    #pragma unroll
    for (int i = 0; i < 2; i++)
        #pragma unroll
        for (int j = 0; j < 2; j++) wmma::fill_fragment(c[i][j], 0.f);

    for (int k0 = 0; k0 < FIN; k0 += 64) {
        #pragma unroll
        for (int i = 0; i < 8; i++) {
            int idx = t + i * 128;
            int r = idx >> 4, c4 = idx & 15;
            float4 v = *(const float4*)&x[(size_t)(row0 + r) * FIN + k0 + c4 * 4];
            v.x = f2tf32(v.x); v.y = f2tf32(v.y); v.z = f2tf32(v.z); v.w = f2tf32(v.w);
            *(float4*)&Xs[r][c4 * 4] = v;
            float4 w = *(const float4*)&W[(size_t)(k0 + r) * HD + col0 + c4 * 4];
            w.x = f2tf32(w.x); w.y = f2tf32(w.y); w.z = f2tf32(w.z); w.w = f2tf32(w.w);
            *(float4*)&Ws[r][c4 * 4] = w;
        }
        __syncthreads();
        #pragma unroll
        for (int kk = 0; kk < 8; kk++) {
            wmma::fragment<wmma::matrix_a, 16, 16, 8, wmma::precision::tf32, wmma::row_major> a[2];
            wmma::fragment<wmma::matrix_b, 16, 16, 8, wmma::precision::tf32, wmma::row_major> bfr[2];
            #pragma unroll
            for (int i = 0; i < 2; i++)
                wmma::load_matrix_sync(a[i], &Xs[warp_m + 16 * i][kk * 8], 72);
            #pragma unroll
            for (int j = 0; j < 2; j++)
                wmma::load_matrix_sync(bfr[j], &Ws[kk * 8][warp_n + 16 * j], 72);
            #pragma unroll
            for (int i = 0; i < 2; i++)
                #pragma unroll
                for (int j = 0; j < 2; j++)
                    wmma::mma_sync(c[i][j], a[i], bfr[j], c[i][j]);
        }
        __syncthreads();
    }

    __shared__ float Stage[64][72];
    #pragma unroll
    for (int i = 0; i < 2; i++)
        #pragma unroll
        for (int j = 0; j < 2; j++)
            wmma::store_matrix_sync(&Stage[warp_m + 16 * i][warp_n + 16 * j], c[i][j], 72,
                                    wmma::mem_row_major);
    __syncthreads();

    // bias + fp16 row-major write; keep biased fp32 in Stage for transpose pass
    #pragma unroll
    for (int i = 0; i < 8; i++) {
        int idx = t + i * 128;
        int r = idx >> 4, c4 = idx & 15;
        float4 v = *(float4*)&Stage[r][c4 * 4];
        float4 bb = *(const float4*)&bias[col0 + c4 * 4];
        v.x += bb.x; v.y += bb.y; v.z += bb.z; v.w += bb.w;
        *(float4*)&Stage[r][c4 * 4] = v;
        __half2 p0 = __float22half2_rn(make_float2(v.x, v.y));
        __half2 p1 = __float22half2_rn(make_float2(v.z, v.w));
        *(__half2*)&g_hh[(size_t)(row0 + r) * HD + col0 + c4 * 4] = p0;
        *(__half2*)&g_hh[(size_t)(row0 + r) * HD + col0 + c4 * 4 + 2] = p1;
    }
    __syncthreads();

    // transposed fp16 write: g_hhT[b][hh][d][n]
    const int b = row0 >> 11;
    const int n0 = row0 & (NN - 1);
    const int hh = col0 >> 6;
    #pragma unroll
    for (int i = 0; i < 8; i++) {
        int idx = t + i * 128;
        int dr = idx >> 4, nc = idx & 15;
        __half2 p0 = __float22half2_rn(make_float2(Stage[nc * 4 + 0][dr], Stage[nc * 4 + 1][dr]));
        __half2 p1 = __float22half2_rn(make_float2(Stage[nc * 4 + 2][dr], Stage[nc * 4 + 3][dr]));
        __half* dst = &g_hhT[((size_t)(b * HH + hh) * DD + dr) * NN + n0 + nc * 4];
        *(__half2*)&dst[0] = p0;
        *(__half2*)&dst[2] = p1;
    }
}

// ---------------------------------------------------------------------------
// K2: register-resident fused attention (mma.m16n8k16 fp16, fp32 accum)
// CTA: 128 threads / 4 warps; 64-row q-tile; 4 CTAs/SM for latency overlap.
// ---------------------------------------------------------------------------
#define STRH 72   // smem tile stride (halfs)

__global__ __launch_bounds__(128, 4) void k_fused() {
    __shared__ __half bufK[2][64 * STRH];
    __shared__ __half bufV[2][64 * STRH];   // transposed: [d][m]

    const int t = threadIdx.x;
    const int lane = t & 31;
    const int wid = t >> 5;                 // 0..3
    const int g = lane >> 2;
    const int q = lane & 3;
    const int row0 = blockIdx.x * 64;
    const int bh = blockIdx.y;
    const int b = bh >> 3, hh = bh & 7;

    const __half* Hb = g_hh + (size_t)b * NN * HD + hh * DD;
    const __half* HTb = g_hhT + (size_t)bh * DD * NN;
    const int r_lo = row0 + wid * 16 + g;
    const int r_hi = r_lo + 8;

    // prefetch tile 0: K row-major 64x64 fp16 + V transposed 64x64 fp16
    {
        #pragma unroll
        for (int k = 0; k < 4; k++) {
            int c = t + k * 128;             // 0..511
            int r = c >> 3, seg = c & 7;
            unsigned dk = (unsigned)__cvta_generic_to_shared(&bufK[0][r * STRH + seg * 8]);
            asm volatile("cp.async.ca.shared.global [%0], [%1], 16;"
                         :: "r"(dk), "l"(&Hb[(size_t)r * HD + seg * 8]));
            unsigned dv = (unsigned)__cvta_generic_to_shared(&bufV[0][r * STRH + seg * 8]);
            asm volatile("cp.async.ca.shared.global [%0], [%1], 16;"
                         :: "r"(dv), "l"(&HTb[(size_t)r * NN + seg * 8]));
        }
        asm volatile("cp.async.commit_group;");
    }

    // Q fragments fp16 (half2 pairs)
    unsigned Qa[4][4];
    #pragma unroll
    for (int kc = 0; kc < 4; kc++) {
        Qa[kc][0] = *(const unsigned*)&Hb[(size_t)r_lo * HD + 16 * kc + 2 * q];
        Qa[kc][1] = *(const unsigned*)&Hb[(size_t)r_hi * HD + 16 * kc + 2 * q];
        Qa[kc][2] = *(const unsigned*)&Hb[(size_t)r_lo * HD + 16 * kc + 8 + 2 * q];
        Qa[kc][3] = *(const unsigned*)&Hb[(size_t)r_hi * HD + 16 * kc + 8 + 2 * q];
    }

    float Oa[8][4];
    #pragma unroll
    for (int f = 0; f < 8; f++)
        #pragma unroll
        for (int e = 0; e < 4; e++) Oa[f][e] = 0.f;
    float rs_lo = 0.f, rs_hi = 0.f;

    const unsigned* mrow_lo = &g_mask[((size_t)b * NN + r_lo) * NW];
    const unsigned* mrow_hi = &g_mask[((size_t)b * NN + r_hi) * NW];
    __half* Srow_lo = &g_S[((size_t)bh * NN + r_lo) * NN];
    __half* Srow_hi = &g_S[((size_t)bh * NN + r_hi) * NN];

    for (int it = 0; it < 32; it++) {
        const int m0 = it * 64;
        asm volatile("cp.async.wait_group 0;");
        __syncthreads();

        if (it < 31) {
            #pragma unroll
            for (int k = 0; k < 4; k++) {
                int c = t + k * 128;
                int r = c >> 3, seg = c & 7;
                unsigned dk = (unsigned)__cvta_generic_to_shared(
                    &bufK[(it + 1) & 1][r * STRH + seg * 8]);
                asm volatile("cp.async.ca.shared.global [%0], [%1], 16;"
                             :: "r"(dk), "l"(&Hb[(size_t)(m0 + 64 + r) * HD + seg * 8]));
                unsigned dv = (unsigned)__cvta_generic_to_shared(
                    &bufV[(it + 1) & 1][r * STRH + seg * 8]);
                asm volatile("cp.async.ca.shared.global [%0], [%1], 16;"
                             :: "r"(dv), "l"(&HTb[(size_t)r * NN + m0 + 64 + seg * 8]));
            }
            asm volatile("cp.async.commit_group;");
        }

        const __half* Kb = bufK[it & 1];
        const __half* Vb = bufV[it & 1];

        const unsigned m00 = __ldg(&mrow_lo[it * 2]);
        const unsigned m01 = __ldg(&mrow_lo[it * 2 + 1]);
        const unsigned m10 = __ldg(&mrow_hi[it * 2]);
        const unsigned m11 = __ldg(&mrow_hi[it * 2 + 1]);

        // ---- S = Q K^T  (32 mma, B = half2 LDS) ----
        float Sa[8][4];
        #pragma unroll
        for (int f = 0; f < 8; f++)
            #pragma unroll
            for (int e = 0; e < 4; e++) Sa[f][e] = 0.f;

        #pragma unroll
        for (int f = 0; f < 8; f++) {
            const unsigned* kr = (const unsigned*)&Kb[(8 * f + g) * STRH];
            #pragma unroll
            for (int kc = 0; kc < 4; kc++) {
                unsigned b0 = kr[8 * kc + q];
                unsigned b1 = kr[8 * kc + 4 + q];
                mma_f16(Sa[f], Qa[kc][0], Qa[kc][1], Qa[kc][2], Qa[kc][3], b0, b1);
            }
        }

        // ---- mask + e = 2^(s*log2e/8 - 14) + rowsum + pack half2 + stream E ----
        unsigned H01[8], H23[8];
        #pragma unroll
        for (int f = 0; f < 8; f++) {
            const unsigned wlo = (f < 4) ? m00 : m01;
            const unsigned whi = (f < 4) ? m10 : m11;
            const int sh = (8 * f + 2 * q) & 31;
            float e0 = ((wlo >> sh) & 1u)       ? exp2f(fmaf(Sa[f][0], L2E8, -14.f)) : 0.f;
            float e1 = ((wlo >> (sh + 1)) & 1u) ? exp2f(fmaf(Sa[f][1], L2E8, -14.f)) : 0.f;
            float e2 = ((whi >> sh) & 1u)       ? exp2f(fmaf(Sa[f][2], L2E8, -14.f)) : 0.f;
            float e3 = ((whi >> (sh + 1)) & 1u) ? exp2f(fmaf(Sa[f][3], L2E8, -14.f)) : 0.f;
            rs_lo += e0 + e1;
            rs_hi += e2 + e3;
            __half2 p01 = __float22half2_rn(make_float2(e0, e1));
            __half2 p23 = __float22half2_rn(make_float2(e2, e3));
            H01[f] = *(unsigned*)&p01;
            H23[f] = *(unsigned*)&p23;
            __stcs((__half2*)&Srow_lo[m0 + 8 * f + 2 * q], p01);
            __stcs((__half2*)&Srow_hi[m0 + 8 * f + 2 * q], p23);
        }

        // ---- O += E V  (32 mma; A = E half2 fragments) ----
        #pragma unroll
        for (int df = 0; df < 8; df++) {
            const unsigned* vr = (const unsigned*)&Vb[(8 * df + g) * STRH];
            #pragma unroll
            for (int kk = 0; kk < 4; kk++) {
                unsigned b0 = vr[8 * kk + q];
                unsigned b1 = vr[8 * kk + 4 + q];
                mma_f16(Oa[df], H01[2 * kk], H23[2 * kk], H01[2 * kk + 1], H23[2 * kk + 1],
                        b0, b1);
            }
        }
    }

    // ---- epilogue ----
    rs_lo += __shfl_xor_sync(0xffffffffu, rs_lo, 1);
    rs_lo += __shfl_xor_sync(0xffffffffu, rs_lo, 2);
    rs_hi += __shfl_xor_sync(0xffffffffu, rs_hi, 1);
    rs_hi += __shfl_xor_sync(0xffffffffu, rs_hi, 2);
    if (q == 0) {
        g_rowsum[(size_t)bh * NN + r_lo] = rs_lo;
        g_rowsum[(size_t)bh * NN + r_hi] = rs_hi;
    }
    const float inv_lo = 1.f / rs_lo;
    const float inv_hi = 1.f / rs_hi;
    float* O_lo = &g_O[((size_t)b * NN + r_lo) * HD + hh * DD];
    float* O_hi = &g_O[((size_t)b * NN + r_hi) * HD + hh * DD];
    #pragma unroll
    for (int df = 0; df < 8; df++) {
        *(float2*)&O_lo[8 * df + 2 * q] = make_float2(Oa[df][0] * inv_lo, Oa[df][1] * inv_lo);
        *(float2*)&O_hi[8 * df + 2 * q] = make_float2(Oa[df][2] * inv_hi, Oa[df][3] * inv_hi);
    }
}

// ---------------------------------------------------------------------------
// K3: mean over heads of p = e / rowsum  -> out_mean  (fp16 E)
// ---------------------------------------------------------------------------
__global__ void k_mean(float* __restrict__ out_mean) {
    __shared__ float inv[HH];
    const int row = blockIdx.x;
    const int b = row >> 11;
    const int n = row & (NN - 1);
    const int t = threadIdx.x;

    if (t < HH) inv[t] = 0.125f / g_rowsum[(size_t)(b * HH + t) * NN + n];
    __syncthreads();

    float* mrow = out_mean + (size_t)row * NN;
    #pragma unroll
    for (int c4 = t; c4 < NN / 4; c4 += 256) {
        float4 acc = make_float4(0.f, 0.f, 0.f, 0.f);
        #pragma unroll
        for (int h = 0; h < HH; h++) {
            const __half2* ep = (const __half2*)&g_S[((size_t)(b * HH + h) * NN + n) * NN + c4 * 4];
            float2 lo = __half22float2(__ldcs(&ep[0]));
            float2 hi = __half22float2(__ldcs(&ep[1]));
            float iv = inv[h];
            acc.x += lo.x * iv; acc.y += lo.y * iv;
            acc.z += hi.x * iv; acc.w += hi.y * iv;
        }
        *(float4*)&mrow[c4 * 4] = acc;
    }
}

// ---------------------------------------------------------------------------
// K5: LayerNorm -> out
// ---------------------------------------------------------------------------
__global__ void k_ln(const float* __restrict__ gamma, const float* __restrict__ beta,
                     float* __restrict__ out) {
    __shared__ float red[128];
    __shared__ float red2[128];

    const int row = blockIdx.x;
    const int t = threadIdx.x;
    const float* v = g_O + (size_t)row * HD;

    float s = 0.f, s2 = 0.f;
    float vals[4];
    #pragma unroll
    for (int i = 0; i < 4; i++) {
        vals[i] = v[t + i * 128];
        s += vals[i];
        s2 += vals[i] * vals[i];
    }
    red[t] = s; red2[t] = s2;
    __syncthreads();
    for (int st = 64; st > 0; st >>= 1) {
        if (t < st) { red[t] += red[t + st]; red2[t] += red2[t + st]; }
        __syncthreads();
    }
    const float mu = red[0] * (1.f / HD);
    const float var = red2[0] * (1.f / HD) - mu * mu;
    const float rstd = rsqrtf(var + EPS);

    float* orow = out + (size_t)row * HD;
    #pragma unroll
    for (int i = 0; i < 4; i++) {
        int c = t + i * 128;
        orow[c] = (vals[i] - mu) * rstd * gamma[c] + beta[c];
    }
}

// ---------------------------------------------------------------------------
extern "C" void kernel_launch(void* const* d_in, const int* in_sizes, int n_in,
                              void* d_out, int out_size) {
    const float* x     = (const float*)d_in[0];
    const int*   adj   = (const int*)d_in[1];
    const float* W_w   = (const float*)d_in[2];
    const float* W_b   = (const float*)d_in[3];
    const float* gamma = (const float*)d_in[4];
    const float* beta  = (const float*)d_in[5];
    float* out = (float*)d_out;
    float* out_mean = out + (size_t)BB * NN * HD;

    k_pack<<<BB * NN, 256>>>(adj);
    k_proj<<<dim3(HD / 64, (BB * NN) / 64), 128>>>(x, W_w, W_b);
    k_fused<<<dim3(NN / 64, BB * HH), 128>>>();
    k_mean<<<BB * NN, 256>>>(out_mean);
    k_ln<<<BB * NN, 128>>>(gamma, beta, out);
}

// round 13
// speedup vs baseline: 1.0023x; 1.0023x over previous
#include <cuda_runtime.h>
#include <cuda_bf16.h>
#include <cuda_fp16.h>
#include <math_constants.h>
#include <mma.h>

using namespace nvcuda;

#define BB 2
#define NN 2048
#define HH 8
#define DD 64
#define FIN 512
#define HD 512
#define EPS 1e-5f
#define SCALE 0.125f
#define BIAS14 9.7040605f   // 14*ln2: e = exp(s/8)*2^-14 (exact power-of-2 scale)
#define NW (NN / 32)

// Device scratch
__device__ __half g_hh[BB * NN * HD];                  // projected features fp16 row-major
__device__ __half g_hhT[BB * HH * DD * NN];            // [b][h][d][n] fp16 (for V-phase)
__device__ __half g_S[(size_t)BB * HH * NN * NN];      // scaled exp values fp16
__device__ float g_O[BB * NN * HD];
__device__ float g_rowsum[BB * HH * NN];
__device__ unsigned g_mask[(size_t)BB * NN * NW];

__device__ __forceinline__ float f2tf32(float x) {
    float r;
    asm("cvt.rna.tf32.f32 %0, %1;" : "=f"(r) : "f"(x));
    return r;
}

__device__ __forceinline__ void mma_f16(float d[4], unsigned a0, unsigned a1,
                                        unsigned a2, unsigned a3,
                                        unsigned b0, unsigned b1) {
    asm volatile(
        "mma.sync.aligned.m16n8k16.row.col.f32.f16.f16.f32 "
        "{%0,%1,%2,%3}, {%4,%5,%6,%7}, {%8,%9}, {%0,%1,%2,%3};"
        : "+f"(d[0]), "+f"(d[1]), "+f"(d[2]), "+f"(d[3])
        : "r"(a0), "r"(a1), "r"(a2), "r"(a3), "r"(b0), "r"(b1));
}

// ---------------------------------------------------------------------------
// K0: pack adj -> bitmask
// ---------------------------------------------------------------------------
__global__ void k_pack(const int* __restrict__ adj) {
    const int row = blockIdx.x;
    const int t = threadIdx.x;
    const int warp = t >> 5, lane = t & 31;
    const int* arow = adj + (size_t)row * NN;
    #pragma unroll
    for (int j = warp; j < NW; j += 8) {
        unsigned bit = (arow[j * 32 + lane] != 0) ? 1u : 0u;
        unsigned word = __ballot_sync(0xffffffffu, bit);
        if (lane == 0) g_mask[(size_t)row * NW + j] = word;
    }
}

// ---------------------------------------------------------------------------
// K1: h = x @ W + b (tf32 wmma, 128x64 tile / 256 threads)
// writes fp16 g_hh + transposed g_hhT
// ---------------------------------------------------------------------------
__global__ __launch_bounds__(256, 2) void k_proj(const float* __restrict__ x,
                                                 const float* __restrict__ W,
                                                 const float* __restrict__ bias) {
    __shared__ float Xs[128][72];
    __shared__ float Ws[64][72];

    const int t = threadIdx.x;
    const int wid = t >> 5;                   // 0..7
    const int warp_m = (wid & 3) * 32;        // 0,32,64,96
    const int warp_n = (wid >> 2) * 32;       // 0,32
    const int row0 = blockIdx.y * 128;
    const int col0 = blockIdx.x * 64;

    wmma::fragment<wmma::accumulator, 16, 16, 8, float> c[2][2];
    #pragma unroll
    for (int i = 0; i < 2; i++)
        #pragma unroll
        for (int j = 0; j < 2; j++) wmma::fill_fragment(c[i][j], 0.f);

    for (int k0 = 0; k0 < FIN; k0 += 64) {
        // X tile 128x64 (8 float4/thread)
        #pragma unroll
        for (int i = 0; i < 8; i++) {
            int idx = t + i * 256;
            int r = idx >> 4, c4 = idx & 15;
            float4 v = *(const float4*)&x[(size_t)(row0 + r) * FIN + k0 + c4 * 4];
            v.x = f2tf32(v.x); v.y = f2tf32(v.y); v.z = f2tf32(v.z); v.w = f2tf32(v.w);
            *(float4*)&Xs[r][c4 * 4] = v;
        }
        // W tile 64x64 (4 float4/thread)
        #pragma unroll
        for (int i = 0; i < 4; i++) {
            int idx = t + i * 256;
            int r = idx >> 4, c4 = idx & 15;
            float4 w = *(const float4*)&W[(size_t)(k0 + r) * HD + col0 + c4 * 4];
            w.x = f2tf32(w.x); w.y = f2tf32(w.y); w.z = f2tf32(w.z); w.w = f2tf32(w.w);
            *(float4*)&Ws[r][c4 * 4] = w;
        }
        __syncthreads();
        #pragma unroll
        for (int kk = 0; kk < 8; kk++) {
            wmma::fragment<wmma::matrix_a, 16, 16, 8, wmma::precision::tf32, wmma::row_major> a[2];
            wmma::fragment<wmma::matrix_b, 16, 16, 8, wmma::precision::tf32, wmma::row_major> bfr[2];
            #pragma unroll
            for (int i = 0; i < 2; i++)
                wmma::load_matrix_sync(a[i], &Xs[warp_m + 16 * i][kk * 8], 72);
            #pragma unroll
            for (int j = 0; j < 2; j++)
                wmma::load_matrix_sync(bfr[j], &Ws[kk * 8][warp_n + 16 * j], 72);
            #pragma unroll
            for (int i = 0; i < 2; i++)
                #pragma unroll
                for (int j = 0; j < 2; j++)
                    wmma::mma_sync(c[i][j], a[i], bfr[j], c[i][j]);
        }
        __syncthreads();
    }

    // stage result into Xs (128x64 fits), add bias
    #pragma unroll
    for (int i = 0; i < 2; i++)
        #pragma unroll
        for (int j = 0; j < 2; j++)
            wmma::store_matrix_sync(&Xs[warp_m + 16 * i][warp_n + 16 * j], c[i][j], 72,
                                    wmma::mem_row_major);
    __syncthreads();

    // bias + fp16 row-major write; keep biased fp32 in Xs for transpose pass
    #pragma unroll
    for (int i = 0; i < 8; i++) {
        int idx = t + i * 256;
        int r = idx >> 4, c4 = idx & 15;
        float4 v = *(float4*)&Xs[r][c4 * 4];
        float4 bb = *(const float4*)&bias[col0 + c4 * 4];
        v.x += bb.x; v.y += bb.y; v.z += bb.z; v.w += bb.w;
        *(float4*)&Xs[r][c4 * 4] = v;
        __half2 p0 = __float22half2_rn(make_float2(v.x, v.y));
        __half2 p1 = __float22half2_rn(make_float2(v.z, v.w));
        *(__half2*)&g_hh[(size_t)(row0 + r) * HD + col0 + c4 * 4] = p0;
        *(__half2*)&g_hh[(size_t)(row0 + r) * HD + col0 + c4 * 4 + 2] = p1;
    }
    __syncthreads();

    // transposed fp16 write: g_hhT[b][hh][d][n], n-range 128
    const int b = row0 >> 11;
    const int n0 = row0 & (NN - 1);
    const int hh = col0 >> 6;
    #pragma unroll
    for (int i = 0; i < 8; i++) {
        int idx = t + i * 256;
        int dr = idx >> 5, nc = idx & 31;     // d 0..63, n-chunk 0..31 (x4)
        __half2 p0 = __float22half2_rn(make_float2(Xs[nc * 4 + 0][dr], Xs[nc * 4 + 1][dr]));
        __half2 p1 = __float22half2_rn(make_float2(Xs[nc * 4 + 2][dr], Xs[nc * 4 + 3][dr]));
        __half* dst = &g_hhT[((size_t)(b * HH + hh) * DD + dr) * NN + n0 + nc * 4];
        *(__half2*)&dst[0] = p0;
        *(__half2*)&dst[2] = p1;
    }
}

// ---------------------------------------------------------------------------
// K2: register-resident fused attention (mma.m16n8k16 fp16, fp32 accum)
// CTA: 256 threads / 8 warps; 128-row q-tile; 2 CTAs/SM. (R11 config)
// ---------------------------------------------------------------------------
#define STRH 72   // smem tile stride (halfs)

__global__ __launch_bounds__(256, 2) void k_fused() {
    __shared__ __half bufK[2][64 * STRH];
    __shared__ __half bufV[2][64 * STRH];   // transposed: [d][m]

    const int t = threadIdx.x;
    const int lane = t & 31;
    const int wid = t >> 5;
    const int g = lane >> 2;
    const int q = lane & 3;
    const int row0 = blockIdx.x * 128;
    const int bh = blockIdx.y;
    const int b = bh >> 3, hh = bh & 7;

    const __half* Hb = g_hh + (size_t)b * NN * HD + hh * DD;
    const __half* HTb = g_hhT + (size_t)bh * DD * NN;
    const int r_lo = row0 + wid * 16 + g;
    const int r_hi = r_lo + 8;

    // prefetch tile 0: K row-major 64x64 fp16 + V transposed 64x64 fp16
    {
        #pragma unroll
        for (int k = 0; k < 2; k++) {
            int c = t + k * 256;             // 0..511
            int r = c >> 3, seg = c & 7;
            unsigned dk = (unsigned)__cvta_generic_to_shared(&bufK[0][r * STRH + seg * 8]);
            asm volatile("cp.async.ca.shared.global [%0], [%1], 16;"
                         :: "r"(dk), "l"(&Hb[(size_t)r * HD + seg * 8]));
            unsigned dv = (unsigned)__cvta_generic_to_shared(&bufV[0][r * STRH + seg * 8]);
            asm volatile("cp.async.ca.shared.global [%0], [%1], 16;"
                         :: "r"(dv), "l"(&HTb[(size_t)r * NN + seg * 8]));
        }
        asm volatile("cp.async.commit_group;");
    }

    // Q fragments fp16 (half2 pairs)
    unsigned Qa[4][4];
    #pragma unroll
    for (int kc = 0; kc < 4; kc++) {
        Qa[kc][0] = *(const unsigned*)&Hb[(size_t)r_lo * HD + 16 * kc + 2 * q];
        Qa[kc][1] = *(const unsigned*)&Hb[(size_t)r_hi * HD + 16 * kc + 2 * q];
        Qa[kc][2] = *(const unsigned*)&Hb[(size_t)r_lo * HD + 16 * kc + 8 + 2 * q];
        Qa[kc][3] = *(const unsigned*)&Hb[(size_t)r_hi * HD + 16 * kc + 8 + 2 * q];
    }

    float Oa[8][4];
    #pragma unroll
    for (int f = 0; f < 8; f++)
        #pragma unroll
        for (int e = 0; e < 4; e++) Oa[f][e] = 0.f;
    float rs_lo = 0.f, rs_hi = 0.f;

    const unsigned* mrow_lo = &g_mask[((size_t)b * NN + r_lo) * NW];
    const unsigned* mrow_hi = &g_mask[((size_t)b * NN + r_hi) * NW];
    __half* Srow_lo = &g_S[((size_t)bh * NN + r_lo) * NN];
    __half* Srow_hi = &g_S[((size_t)bh * NN + r_hi) * NN];

    for (int it = 0; it < 32; it++) {
        const int m0 = it * 64;
        asm volatile("cp.async.wait_group 0;");
        __syncthreads();

        if (it < 31) {
            #pragma unroll
            for (int k = 0; k < 2; k++) {
                int c = t + k * 256;
                int r = c >> 3, seg = c & 7;
                unsigned dk = (unsigned)__cvta_generic_to_shared(
                    &bufK[(it + 1) & 1][r * STRH + seg * 8]);
                asm volatile("cp.async.ca.shared.global [%0], [%1], 16;"
                             :: "r"(dk), "l"(&Hb[(size_t)(m0 + 64 + r) * HD + seg * 8]));
                unsigned dv = (unsigned)__cvta_generic_to_shared(
                    &bufV[(it + 1) & 1][r * STRH + seg * 8]);
                asm volatile("cp.async.ca.shared.global [%0], [%1], 16;"
                             :: "r"(dv), "l"(&HTb[(size_t)r * NN + m0 + 64 + seg * 8]));
            }
            asm volatile("cp.async.commit_group;");
        }

        const __half* Kb = bufK[it & 1];
        const __half* Vb = bufV[it & 1];

        const unsigned m00 = __ldg(&mrow_lo[it * 2]);
        const unsigned m01 = __ldg(&mrow_lo[it * 2 + 1]);
        const unsigned m10 = __ldg(&mrow_hi[it * 2]);
        const unsigned m11 = __ldg(&mrow_hi[it * 2 + 1]);

        // ---- S = Q K^T  (32 mma, B = half2 LDS) ----
        float Sa[8][4];
        #pragma unroll
        for (int f = 0; f < 8; f++)
            #pragma unroll
            for (int e = 0; e < 4; e++) Sa[f][e] = 0.f;

        #pragma unroll
        for (int f = 0; f < 8; f++) {
            const unsigned* kr = (const unsigned*)&Kb[(8 * f + g) * STRH];
            #pragma unroll
            for (int kc = 0; kc < 4; kc++) {
                unsigned b0 = kr[8 * kc + q];
                unsigned b1 = kr[8 * kc + 4 + q];
                mma_f16(Sa[f], Qa[kc][0], Qa[kc][1], Qa[kc][2], Qa[kc][3], b0, b1);
            }
        }

        // ---- mask + exp(s/8 - 14ln2) + rowsum + pack half2 + stream E ----
        unsigned H01[8], H23[8];
        #pragma unroll
        for (int f = 0; f < 8; f++) {
            const unsigned wlo = (f < 4) ? m00 : m01;
            const unsigned whi = (f < 4) ? m10 : m11;
            const int sh = (8 * f + 2 * q) & 31;
            float e0 = ((wlo >> sh) & 1u)       ? __expf(fmaf(Sa[f][0], SCALE, -BIAS14)) : 0.f;
            float e1 = ((wlo >> (sh + 1)) & 1u) ? __expf(fmaf(Sa[f][1], SCALE, -BIAS14)) : 0.f;
            float e2 = ((whi >> sh) & 1u)       ? __expf(fmaf(Sa[f][2], SCALE, -BIAS14)) : 0.f;
            float e3 = ((whi >> (sh + 1)) & 1u) ? __expf(fmaf(Sa[f][3], SCALE, -BIAS14)) : 0.f;
            rs_lo += e0 + e1;
            rs_hi += e2 + e3;
            __half2 p01 = __float22half2_rn(make_float2(e0, e1));
            __half2 p23 = __float22half2_rn(make_float2(e2, e3));
            H01[f] = *(unsigned*)&p01;
            H23[f] = *(unsigned*)&p23;
            __stcs((__half2*)&Srow_lo[m0 + 8 * f + 2 * q], p01);
            __stcs((__half2*)&Srow_hi[m0 + 8 * f + 2 * q], p23);
        }

        // ---- O += E V  (32 mma; A = E half2 fragments, NO shuffles) ----
        #pragma unroll
        for (int df = 0; df < 8; df++) {
            const unsigned* vr = (const unsigned*)&Vb[(8 * df + g) * STRH];
            #pragma unroll
            for (int kk = 0; kk < 4; kk++) {
                unsigned b0 = vr[8 * kk + q];
                unsigned b1 = vr[8 * kk + 4 + q];
                mma_f16(Oa[df], H01[2 * kk], H23[2 * kk], H01[2 * kk + 1], H23[2 * kk + 1],
                        b0, b1);
            }
        }
    }

    // ---- epilogue ----
    rs_lo += __shfl_xor_sync(0xffffffffu, rs_lo, 1);
    rs_lo += __shfl_xor_sync(0xffffffffu, rs_lo, 2);
    rs_hi += __shfl_xor_sync(0xffffffffu, rs_hi, 1);
    rs_hi += __shfl_xor_sync(0xffffffffu, rs_hi, 2);
    if (q == 0) {
        g_rowsum[(size_t)bh * NN + r_lo] = rs_lo;
        g_rowsum[(size_t)bh * NN + r_hi] = rs_hi;
    }
    const float inv_lo = 1.f / rs_lo;
    const float inv_hi = 1.f / rs_hi;
    float* O_lo = &g_O[((size_t)b * NN + r_lo) * HD + hh * DD];
    float* O_hi = &g_O[((size_t)b * NN + r_hi) * HD + hh * DD];
    #pragma unroll
    for (int df = 0; df < 8; df++) {
        *(float2*)&O_lo[8 * df + 2 * q] = make_float2(Oa[df][0] * inv_lo, Oa[df][1] * inv_lo);
        *(float2*)&O_hi[8 * df + 2 * q] = make_float2(Oa[df][2] * inv_hi, Oa[df][3] * inv_hi);
    }
}

// ---------------------------------------------------------------------------
// K3: mean over heads of p = e / rowsum -> out_mean
// 256 threads; thread t owns output cols [8t, 8t+8): one LDG.128 per head.
// ---------------------------------------------------------------------------
__global__ void k_mean(float* __restrict__ out_mean) {
    __shared__ float inv[HH];
    const int row = blockIdx.x;
    const int b = row >> 11;
    const int n = row & (NN - 1);
    const int t = threadIdx.x;

    if (t < HH) inv[t] = 0.125f / g_rowsum[(size_t)(b * HH + t) * NN + n];
    __syncthreads();

    float acc[8];
    #pragma unroll
    for (int i = 0; i < 8; i++) acc[i] = 0.f;

    #pragma unroll
    for (int h = 0; h < HH; h++) {
        const float4 raw = __ldcs((const float4*)&g_S[((size_t)(b * HH + h) * NN + n) * NN + t * 8]);
        const __half2* hp = (const __half2*)&raw;
        const float iv = inv[h];
        #pragma unroll
        for (int j = 0; j < 4; j++) {
            float2 p = __half22float2(hp[j]);
            acc[2 * j]     += p.x * iv;
            acc[2 * j + 1] += p.y * iv;
        }
    }

    float* mrow = out_mean + (size_t)row * NN + t * 8;
    float4 o0 = make_float4(acc[0], acc[1], acc[2], acc[3]);
    float4 o1 = make_float4(acc[4], acc[5], acc[6], acc[7]);
    *(float4*)&mrow[0] = o0;
    *(float4*)&mrow[4] = o1;
}

// ---------------------------------------------------------------------------
// K5: LayerNorm -> out
// ---------------------------------------------------------------------------
__global__ void k_ln(const float* __restrict__ gamma, const float* __restrict__ beta,
                     float* __restrict__ out) {
    __shared__ float red[128];
    __shared__ float red2[128];

    const int row = blockIdx.x;
    const int t = threadIdx.x;
    const float* v = g_O + (size_t)row * HD;

    float s = 0.f, s2 = 0.f;
    float vals[4];
    #pragma unroll
    for (int i = 0; i < 4; i++) {
        vals[i] = v[t + i * 128];
        s += vals[i];
        s2 += vals[i] * vals[i];
    }
    red[t] = s; red2[t] = s2;
    __syncthreads();
    for (int st = 64; st > 0; st >>= 1) {
        if (t < st) { red[t] += red[t + st]; red2[t] += red2[t + st]; }
        __syncthreads();
    }
    const float mu = red[0] * (1.f / HD);
    const float var = red2[0] * (1.f / HD) - mu * mu;
    const float rstd = rsqrtf(var + EPS);

    float* orow = out + (size_t)row * HD;
    #pragma unroll
    for (int i = 0; i < 4; i++) {
        int c = t + i * 128;
        orow[c] = (vals[i] - mu) * rstd * gamma[c] + beta[c];
    }
}

// ---------------------------------------------------------------------------
extern "C" void kernel_launch(void* const* d_in, const int* in_sizes, int n_in,
                              void* d_out, int out_size) {
    const float* x     = (const float*)d_in[0];
    const int*   adj   = (const int*)d_in[1];
    const float* W_w   = (const float*)d_in[2];
    const float* W_b   = (const float*)d_in[3];
    const float* gamma = (const float*)d_in[4];
    const float* beta  = (const float*)d_in[5];
    float* out = (float*)d_out;
    float* out_mean = out + (size_t)BB * NN * HD;

    k_pack<<<BB * NN, 256>>>(adj);
    k_proj<<<dim3(HD / 64, (BB * NN) / 128), 256>>>(x, W_w, W_b);
    k_fused<<<dim3(NN / 128, BB * HH), 256>>>();
    k_mean<<<BB * NN, 256>>>(out_mean);
    k_ln<<<BB * NN, 128>>>(gamma, beta, out);
}

// round 14
// speedup vs baseline: 1.0403x; 1.0379x over previous
#include <cuda_runtime.h>
#include <cuda_bf16.h>
#include <cuda_fp16.h>
#include <math_constants.h>
#include <mma.h>

using namespace nvcuda;

#define BB 2
#define NN 2048
#define HH 8
#define DD 64
#define FIN 512
#define HD 512
#define EPS 1e-5f
#define SCALE 0.125f
#define BIAS14 9.7040605f   // 14*ln2: e = exp(s/8)*2^-14 (exact power-of-2 scale)
#define NW (NN / 32)

// Device scratch
__device__ __half g_hh[BB * NN * HD];                  // projected features fp16 row-major
__device__ __half g_hhT[BB * HH * DD * NN];            // [b][h][d][n] fp16 (for V-phase)
__device__ __half g_S[(size_t)BB * HH * NN * NN];      // scaled exp values fp16
__device__ float g_O[BB * NN * HD];
__device__ float g_rowsum[BB * HH * NN];
__device__ unsigned g_mask[(size_t)BB * NN * NW];

__device__ __forceinline__ float f2tf32(float x) {
    float r;
    asm("cvt.rna.tf32.f32 %0, %1;" : "=f"(r) : "f"(x));
    return r;
}

__device__ __forceinline__ void mma_f16(float d[4], unsigned a0, unsigned a1,
                                        unsigned a2, unsigned a3,
                                        unsigned b0, unsigned b1) {
    asm volatile(
        "mma.sync.aligned.m16n8k16.row.col.f32.f16.f16.f32 "
        "{%0,%1,%2,%3}, {%4,%5,%6,%7}, {%8,%9}, {%0,%1,%2,%3};"
        : "+f"(d[0]), "+f"(d[1]), "+f"(d[2]), "+f"(d[3])
        : "r"(a0), "r"(a1), "r"(a2), "r"(a3), "r"(b0), "r"(b1));
}

// ---------------------------------------------------------------------------
// K1: h = x @ W + b (tf32 wmma, 128x64 tile / 256 threads)
// z=0 blocks: projection; z=1 blocks: pack adj -> bitmask (runs concurrently)
// ---------------------------------------------------------------------------
__global__ __launch_bounds__(256, 2) void k_proj(const float* __restrict__ x,
                                                 const float* __restrict__ W,
                                                 const float* __restrict__ bias,
                                                 const int* __restrict__ adj) {
    __shared__ float Xs[128][72];
    __shared__ float Ws[64][72];

    const int t = threadIdx.x;

    if (blockIdx.z == 1) {
        // ---- pack branch: 256 CTAs x 16 rows each ----
        const int base = (blockIdx.y * gridDim.x + blockIdx.x) * 16;
        const int warp = t >> 5, lane = t & 31;
        #pragma unroll
        for (int rr = 0; rr < 2; rr++) {
            const int row = base + warp * 2 + rr;
            const int* arow = adj + (size_t)row * NN;
            #pragma unroll
            for (int j = 0; j < NW; j++) {
                unsigned bit = (arow[j * 32 + lane] != 0) ? 1u : 0u;
                unsigned word = __ballot_sync(0xffffffffu, bit);
                if (lane == 0) g_mask[(size_t)row * NW + j] = word;
            }
        }
        return;
    }

    const int wid = t >> 5;                   // 0..7
    const int warp_m = (wid & 3) * 32;        // 0,32,64,96
    const int warp_n = (wid >> 2) * 32;       // 0,32
    const int row0 = blockIdx.y * 128;
    const int col0 = blockIdx.x * 64;

    wmma::fragment<wmma::accumulator, 16, 16, 8, float> c[2][2];
    #pragma unroll
    for (int i = 0; i < 2; i++)
        #pragma unroll
        for (int j = 0; j < 2; j++) wmma::fill_fragment(c[i][j], 0.f);

    for (int k0 = 0; k0 < FIN; k0 += 64) {
        #pragma unroll
        for (int i = 0; i < 8; i++) {
            int idx = t + i * 256;
            int r = idx >> 4, c4 = idx & 15;
            float4 v = *(const float4*)&x[(size_t)(row0 + r) * FIN + k0 + c4 * 4];
            v.x = f2tf32(v.x); v.y = f2tf32(v.y); v.z = f2tf32(v.z); v.w = f2tf32(v.w);
            *(float4*)&Xs[r][c4 * 4] = v;
        }
        #pragma unroll
        for (int i = 0; i < 4; i++) {
            int idx = t + i * 256;
            int r = idx >> 4, c4 = idx & 15;
            float4 w = *(const float4*)&W[(size_t)(k0 + r) * HD + col0 + c4 * 4];
            w.x = f2tf32(w.x); w.y = f2tf32(w.y); w.z = f2tf32(w.z); w.w = f2tf32(w.w);
            *(float4*)&Ws[r][c4 * 4] = w;
        }
        __syncthreads();
        #pragma unroll
        for (int kk = 0; kk < 8; kk++) {
            wmma::fragment<wmma::matrix_a, 16, 16, 8, wmma::precision::tf32, wmma::row_major> a[2];
            wmma::fragment<wmma::matrix_b, 16, 16, 8, wmma::precision::tf32, wmma::row_major> bfr[2];
            #pragma unroll
            for (int i = 0; i < 2; i++)
                wmma::load_matrix_sync(a[i], &Xs[warp_m + 16 * i][kk * 8], 72);
            #pragma unroll
            for (int j = 0; j < 2; j++)
                wmma::load_matrix_sync(bfr[j], &Ws[kk * 8][warp_n + 16 * j], 72);
            #pragma unroll
            for (int i = 0; i < 2; i++)
                #pragma unroll
                for (int j = 0; j < 2; j++)
                    wmma::mma_sync(c[i][j], a[i], bfr[j], c[i][j]);
        }
        __syncthreads();
    }

    #pragma unroll
    for (int i = 0; i < 2; i++)
        #pragma unroll
        for (int j = 0; j < 2; j++)
            wmma::store_matrix_sync(&Xs[warp_m + 16 * i][warp_n + 16 * j], c[i][j], 72,
                                    wmma::mem_row_major);
    __syncthreads();

    // bias + fp16 row-major write; keep biased fp32 in Xs for transpose pass
    #pragma unroll
    for (int i = 0; i < 8; i++) {
        int idx = t + i * 256;
        int r = idx >> 4, c4 = idx & 15;
        float4 v = *(float4*)&Xs[r][c4 * 4];
        float4 bb = *(const float4*)&bias[col0 + c4 * 4];
        v.x += bb.x; v.y += bb.y; v.z += bb.z; v.w += bb.w;
        *(float4*)&Xs[r][c4 * 4] = v;
        __half2 p0 = __float22half2_rn(make_float2(v.x, v.y));
        __half2 p1 = __float22half2_rn(make_float2(v.z, v.w));
        *(__half2*)&g_hh[(size_t)(row0 + r) * HD + col0 + c4 * 4] = p0;
        *(__half2*)&g_hh[(size_t)(row0 + r) * HD + col0 + c4 * 4 + 2] = p1;
    }
    __syncthreads();

    // transposed fp16 write: g_hhT[b][hh][d][n], n-range 128
    const int b = row0 >> 11;
    const int n0 = row0 & (NN - 1);
    const int hh = col0 >> 6;
    #pragma unroll
    for (int i = 0; i < 8; i++) {
        int idx = t + i * 256;
        int dr = idx >> 5, nc = idx & 31;
        __half2 p0 = __float22half2_rn(make_float2(Xs[nc * 4 + 0][dr], Xs[nc * 4 + 1][dr]));
        __half2 p1 = __float22half2_rn(make_float2(Xs[nc * 4 + 2][dr], Xs[nc * 4 + 3][dr]));
        __half* dst = &g_hhT[((size_t)(b * HH + hh) * DD + dr) * NN + n0 + nc * 4];
        *(__half2*)&dst[0] = p0;
        *(__half2*)&dst[2] = p1;
    }
}

// ---------------------------------------------------------------------------
// K2: fused attention (mma.m16n8k16 fp16, fp32 accum), software-pipelined:
// per iter:  exp_it -> S_{it+1} (tensor) -> AV_it (tensor); 3-slot cp.async ring.
// CTA: 256 threads / 8 warps; 128-row q-tile; 2 CTAs/SM.
// ---------------------------------------------------------------------------
#define STRH 72                 // smem tile stride (halfs)
#define TILEH (64 * STRH)       // halfs per tile
#define SLOTH (2 * TILEH)       // K+V per slot
#define FSMEM (3 * SLOTH * 2)   // bytes: 55296

__global__ __launch_bounds__(256, 2) void k_fused() {
    extern __shared__ __half sm[];

    const int t = threadIdx.x;
    const int lane = t & 31;
    const int wid = t >> 5;
    const int g = lane >> 2;
    const int q = lane & 3;
    const int row0 = blockIdx.x * 128;
    const int bh = blockIdx.y;
    const int b = bh >> 3, hh = bh & 7;

    const __half* Hb = g_hh + (size_t)b * NN * HD + hh * DD;
    const __half* HTb = g_hhT + (size_t)bh * DD * NN;
    const int r_lo = row0 + wid * 16 + g;
    const int r_hi = r_lo + 8;

    // prefetch tiles 0,1 into slots 0,1
    #pragma unroll
    for (int tile = 0; tile < 2; tile++) {
        __half* kb = sm + tile * SLOTH;
        __half* vb = kb + TILEH;
        #pragma unroll
        for (int k = 0; k < 2; k++) {
            int c = t + k * 256;
            int r = c >> 3, seg = c & 7;
            unsigned dk = (unsigned)__cvta_generic_to_shared(&kb[r * STRH + seg * 8]);
            asm volatile("cp.async.ca.shared.global [%0], [%1], 16;"
                         :: "r"(dk), "l"(&Hb[(size_t)(tile * 64 + r) * HD + seg * 8]));
            unsigned dv = (unsigned)__cvta_generic_to_shared(&vb[r * STRH + seg * 8]);
            asm volatile("cp.async.ca.shared.global [%0], [%1], 16;"
                         :: "r"(dv), "l"(&HTb[(size_t)r * NN + tile * 64 + seg * 8]));
        }
        asm volatile("cp.async.commit_group;");
    }

    // Q fragments fp16 (half2 pairs)
    unsigned Qa[4][4];
    #pragma unroll
    for (int kc = 0; kc < 4; kc++) {
        Qa[kc][0] = *(const unsigned*)&Hb[(size_t)r_lo * HD + 16 * kc + 2 * q];
        Qa[kc][1] = *(const unsigned*)&Hb[(size_t)r_hi * HD + 16 * kc + 2 * q];
        Qa[kc][2] = *(const unsigned*)&Hb[(size_t)r_lo * HD + 16 * kc + 8 + 2 * q];
        Qa[kc][3] = *(const unsigned*)&Hb[(size_t)r_hi * HD + 16 * kc + 8 + 2 * q];
    }

    float Oa[8][4];
    #pragma unroll
    for (int f = 0; f < 8; f++)
        #pragma unroll
        for (int e = 0; e < 4; e++) Oa[f][e] = 0.f;
    float rs_lo = 0.f, rs_hi = 0.f;

    const unsigned* mrow_lo = &g_mask[((size_t)b * NN + r_lo) * NW];
    const unsigned* mrow_hi = &g_mask[((size_t)b * NN + r_hi) * NW];
    __half* Srow_lo = &g_S[((size_t)bh * NN + r_lo) * NN];
    __half* Srow_hi = &g_S[((size_t)bh * NN + r_hi) * NN];

    // wait tile 0, compute S_0
    asm volatile("cp.async.wait_group 1;");
    __syncthreads();

    float Sa[8][4];
    #pragma unroll
    for (int f = 0; f < 8; f++)
        #pragma unroll
        for (int e = 0; e < 4; e++) Sa[f][e] = 0.f;
    {
        const __half* Kb = sm;   // slot 0
        #pragma unroll
        for (int f = 0; f < 8; f++) {
            const unsigned* kr = (const unsigned*)&Kb[(8 * f + g) * STRH];
            #pragma unroll
            for (int kc = 0; kc < 4; kc++)
                mma_f16(Sa[f], Qa[kc][0], Qa[kc][1], Qa[kc][2], Qa[kc][3],
                        kr[8 * kc + q], kr[8 * kc + 4 + q]);
        }
    }

    for (int it = 0; it < 32; it++) {
        const int m0 = it * 64;

        // ---- exp phase: Sa -> H (half2), rowsum, stream E ----
        const unsigned m00 = __ldg(&mrow_lo[it * 2]);
        const unsigned m01 = __ldg(&mrow_lo[it * 2 + 1]);
        const unsigned m10 = __ldg(&mrow_hi[it * 2]);
        const unsigned m11 = __ldg(&mrow_hi[it * 2 + 1]);

        unsigned H01[8], H23[8];
        #pragma unroll
        for (int f = 0; f < 8; f++) {
            const unsigned wlo = (f < 4) ? m00 : m01;
            const unsigned whi = (f < 4) ? m10 : m11;
            const int sh = (8 * f + 2 * q) & 31;
            float e0 = ((wlo >> sh) & 1u)       ? __expf(fmaf(Sa[f][0], SCALE, -BIAS14)) : 0.f;
            float e1 = ((wlo >> (sh + 1)) & 1u) ? __expf(fmaf(Sa[f][1], SCALE, -BIAS14)) : 0.f;
            float e2 = ((whi >> sh) & 1u)       ? __expf(fmaf(Sa[f][2], SCALE, -BIAS14)) : 0.f;
            float e3 = ((whi >> (sh + 1)) & 1u) ? __expf(fmaf(Sa[f][3], SCALE, -BIAS14)) : 0.f;
            rs_lo += e0 + e1;
            rs_hi += e2 + e3;
            __half2 p01 = __float22half2_rn(make_float2(e0, e1));
            __half2 p23 = __float22half2_rn(make_float2(e2, e3));
            H01[f] = *(unsigned*)&p01;
            H23[f] = *(unsigned*)&p23;
            __stcs((__half2*)&Srow_lo[m0 + 8 * f + 2 * q], p01);
            __stcs((__half2*)&Srow_hi[m0 + 8 * f + 2 * q], p23);
        }

        if (it < 31) {
            __syncthreads();   // all warps done with slot (it-1); tile it+1 about to be used

            // prefetch tile it+2 into slot (it+2)%3 (overwrites slot (it-1)%3 — safe)
            if (it < 30) {
                const int tile = it + 2;
                __half* kb = sm + (tile % 3) * SLOTH;
                __half* vb = kb + TILEH;
                #pragma unroll
                for (int k = 0; k < 2; k++) {
                    int c = t + k * 256;
                    int r = c >> 3, seg = c & 7;
                    unsigned dk = (unsigned)__cvta_generic_to_shared(&kb[r * STRH + seg * 8]);
                    asm volatile("cp.async.ca.shared.global [%0], [%1], 16;"
                                 :: "r"(dk), "l"(&Hb[(size_t)(tile * 64 + r) * HD + seg * 8]));
                    unsigned dv = (unsigned)__cvta_generic_to_shared(&vb[r * STRH + seg * 8]);
                    asm volatile("cp.async.ca.shared.global [%0], [%1], 16;"
                                 :: "r"(dv), "l"(&HTb[(size_t)r * NN + tile * 64 + seg * 8]));
                }
                asm volatile("cp.async.commit_group;");
                asm volatile("cp.async.wait_group 1;");   // tile it+1 complete
            } else {
                asm volatile("cp.async.wait_group 0;");   // tile 31 complete
            }

            // ---- S_{it+1} (tensor; overlaps exp latency, fills slack before AV) ----
            const __half* Kb = sm + ((it + 1) % 3) * SLOTH;
            #pragma unroll
            for (int f = 0; f < 8; f++)
                #pragma unroll
                for (int e = 0; e < 4; e++) Sa[f][e] = 0.f;
            #pragma unroll
            for (int f = 0; f < 8; f++) {
                const unsigned* kr = (const unsigned*)&Kb[(8 * f + g) * STRH];
                #pragma unroll
                for (int kc = 0; kc < 4; kc++)
                    mma_f16(Sa[f], Qa[kc][0], Qa[kc][1], Qa[kc][2], Qa[kc][3],
                            kr[8 * kc + q], kr[8 * kc + 4 + q]);
            }
        }

        // ---- AV_it: O += E V ----
        const __half* Vb = sm + (it % 3) * SLOTH + TILEH;
        #pragma unroll
        for (int df = 0; df < 8; df++) {
            const unsigned* vr = (const unsigned*)&Vb[(8 * df + g) * STRH];
            #pragma unroll
            for (int kk = 0; kk < 4; kk++)
                mma_f16(Oa[df], H01[2 * kk], H23[2 * kk], H01[2 * kk + 1], H23[2 * kk + 1],
                        vr[8 * kk + q], vr[8 * kk + 4 + q]);
        }
    }

    // ---- epilogue ----
    rs_lo += __shfl_xor_sync(0xffffffffu, rs_lo, 1);
    rs_lo += __shfl_xor_sync(0xffffffffu, rs_lo, 2);
    rs_hi += __shfl_xor_sync(0xffffffffu, rs_hi, 1);
    rs_hi += __shfl_xor_sync(0xffffffffu, rs_hi, 2);
    if (q == 0) {
        g_rowsum[(size_t)bh * NN + r_lo] = rs_lo;
        g_rowsum[(size_t)bh * NN + r_hi] = rs_hi;
    }
    const float inv_lo = 1.f / rs_lo;
    const float inv_hi = 1.f / rs_hi;
    float* O_lo = &g_O[((size_t)b * NN + r_lo) * HD + hh * DD];
    float* O_hi = &g_O[((size_t)b * NN + r_hi) * HD + hh * DD];
    #pragma unroll
    for (int df = 0; df < 8; df++) {
        *(float2*)&O_lo[8 * df + 2 * q] = make_float2(Oa[df][0] * inv_lo, Oa[df][1] * inv_lo);
        *(float2*)&O_hi[8 * df + 2 * q] = make_float2(Oa[df][2] * inv_hi, Oa[df][3] * inv_hi);
    }
}

// ---------------------------------------------------------------------------
// K3: LayerNorm (out head) + mean over heads (out tail), one block per row
// ---------------------------------------------------------------------------
__global__ void k_epi(const float* __restrict__ gamma, const float* __restrict__ beta,
                      float* __restrict__ out, float* __restrict__ out_mean) {
    __shared__ float red[256];
    __shared__ float red2[256];
    __shared__ float inv[HH];

    const int row = blockIdx.x;
    const int b = row >> 11;
    const int n = row & (NN - 1);
    const int t = threadIdx.x;

    if (t < HH) inv[t] = 0.125f / g_rowsum[(size_t)(b * HH + t) * NN + n];

    // ---- LayerNorm: each thread owns cols t, t+256 ----
    const float* v = g_O + (size_t)row * HD;
    float v0 = v[t], v1 = v[t + 256];
    red[t] = v0 + v1;
    red2[t] = v0 * v0 + v1 * v1;
    __syncthreads();
    for (int st = 128; st > 0; st >>= 1) {
        if (t < st) { red[t] += red[t + st]; red2[t] += red2[t + st]; }
        __syncthreads();
    }
    const float mu = red[0] * (1.f / HD);
    const float var = red2[0] * (1.f / HD) - mu * mu;
    const float rstd = rsqrtf(var + EPS);

    float* orow = out + (size_t)row * HD;
    orow[t] = (v0 - mu) * rstd * gamma[t] + beta[t];
    orow[t + 256] = (v1 - mu) * rstd * gamma[t + 256] + beta[t + 256];

    // ---- mean over heads: thread t owns cols [8t, 8t+8) ----
    float acc[8];
    #pragma unroll
    for (int i = 0; i < 8; i++) acc[i] = 0.f;

    #pragma unroll
    for (int h = 0; h < HH; h++) {
        const float4 raw = __ldcs((const float4*)&g_S[((size_t)(b * HH + h) * NN + n) * NN + t * 8]);
        const __half2* hp = (const __half2*)&raw;
        const float iv = inv[h];
        #pragma unroll
        for (int j = 0; j < 4; j++) {
            float2 p = __half22float2(hp[j]);
            acc[2 * j]     += p.x * iv;
            acc[2 * j + 1] += p.y * iv;
        }
    }

    float* mrow = out_mean + (size_t)row * NN + t * 8;
    *(float4*)&mrow[0] = make_float4(acc[0], acc[1], acc[2], acc[3]);
    *(float4*)&mrow[4] = make_float4(acc[4], acc[5], acc[6], acc[7]);
}

// ---------------------------------------------------------------------------
extern "C" void kernel_launch(void* const* d_in, const int* in_sizes, int n_in,
                              void* d_out, int out_size) {
    const float* x     = (const float*)d_in[0];
    const int*   adj   = (const int*)d_in[1];
    const float* W_w   = (const float*)d_in[2];
    const float* W_b   = (const float*)d_in[3];
    const float* gamma = (const float*)d_in[4];
    const float* beta  = (const float*)d_in[5];
    float* out = (float*)d_out;
    float* out_mean = out + (size_t)BB * NN * HD;

    cudaFuncSetAttribute(k_fused, cudaFuncAttributeMaxDynamicSharedMemorySize, FSMEM);

    k_proj<<<dim3(HD / 64, (BB * NN) / 128, 2), 256>>>(x, W_w, W_b, adj);
    k_fused<<<dim3(NN / 128, BB * HH), 256, FSMEM>>>();
    k_epi<<<BB * NN, 256>>>(gamma, beta, out, out_mean);
}

// round 15
// speedup vs baseline: 1.1313x; 1.0875x over previous
#include <cuda_runtime.h>
#include <cuda_bf16.h>
#include <cuda_fp16.h>
#include <math_constants.h>
#include <mma.h>

#define BB 2
#define NN 2048
#define HH 8
#define DD 64
#define FIN 512
#define HD 512
#define EPS 1e-5f
#define SCALE 0.125f
#define BIAS14 9.7040605f   // 14*ln2: e = exp(s/8)*2^-14 (exact power-of-2 scale)
#define NW (NN / 32)

// Device scratch
__device__ __half g_hh[BB * NN * HD];                  // projected features fp16 row-major
__device__ __half g_hhT[BB * HH * DD * NN];            // [b][h][d][n] fp16 (for V-phase)
__device__ __half g_S[(size_t)BB * HH * NN * NN];      // scaled exp values fp16
__device__ float g_O[BB * NN * HD];
__device__ float g_rowsum[BB * HH * NN];
__device__ unsigned g_mask[(size_t)BB * NN * NW];

__device__ __forceinline__ void mma_f16(float d[4], unsigned a0, unsigned a1,
                                        unsigned a2, unsigned a3,
                                        unsigned b0, unsigned b1) {
    asm volatile(
        "mma.sync.aligned.m16n8k16.row.col.f32.f16.f16.f32 "
        "{%0,%1,%2,%3}, {%4,%5,%6,%7}, {%8,%9}, {%0,%1,%2,%3};"
        : "+f"(d[0]), "+f"(d[1]), "+f"(d[2]), "+f"(d[3])
        : "r"(a0), "r"(a1), "r"(a2), "r"(a3), "r"(b0), "r"(b1));
}

// ---------------------------------------------------------------------------
// K1: h = x @ W + b  (raw fp16 m16n8k16 mma, 128x64 tile / 256 threads)
// z=0 blocks: projection; z=1 blocks: pack adj -> bitmask (concurrent)
// ---------------------------------------------------------------------------
#define PSTR 72   // smem stride (halfs for tiles, floats for stage)

__global__ __launch_bounds__(256, 2) void k_proj(const float* __restrict__ x,
                                                 const float* __restrict__ W,
                                                 const float* __restrict__ bias,
                                                 const int* __restrict__ adj) {
    __shared__ __align__(16) char smraw[128 * PSTR * 4];   // 36864 B
    __half* Xh = (__half*)smraw;                            // [128][PSTR] fp16
    __half* Wh = (__half*)(smraw + 128 * PSTR * 2);         // [64][PSTR] fp16, [n][k]
    float* Stage = (float*)smraw;                           // [128][PSTR] fp32 (reuse)

    const int t = threadIdx.x;

    if (blockIdx.z == 1) {
        // ---- pack branch: 256 CTAs x 16 rows each ----
        const int base = (blockIdx.y * gridDim.x + blockIdx.x) * 16;
        const int warp = t >> 5, lane = t & 31;
        #pragma unroll
        for (int rr = 0; rr < 2; rr++) {
            const int row = base + warp * 2 + rr;
            const int* arow = adj + (size_t)row * NN;
            #pragma unroll
            for (int j = 0; j < NW; j++) {
                unsigned bit = (arow[j * 32 + lane] != 0) ? 1u : 0u;
                unsigned word = __ballot_sync(0xffffffffu, bit);
                if (lane == 0) g_mask[(size_t)row * NW + j] = word;
            }
        }
        return;
    }

    const int lane = t & 31;
    const int wid = t >> 5;                   // 0..7
    const int g = lane >> 2;
    const int q = lane & 3;
    const int warp_m = (wid & 3) * 32;        // 0,32,64,96
    const int warp_n = (wid >> 2) * 32;       // 0,32
    const int row0 = blockIdx.y * 128;
    const int col0 = blockIdx.x * 64;

    float acc[2][4][4];
    #pragma unroll
    for (int i = 0; i < 2; i++)
        #pragma unroll
        for (int j = 0; j < 4; j++)
            #pragma unroll
            for (int e = 0; e < 4; e++) acc[i][j][e] = 0.f;

    for (int k0 = 0; k0 < FIN; k0 += 64) {
        // X tile 128x64 -> fp16 row-major
        #pragma unroll
        for (int i = 0; i < 8; i++) {
            int idx = t + i * 256;
            int r = idx >> 4, c4 = idx & 15;
            float4 v = *(const float4*)&x[(size_t)(row0 + r) * FIN + k0 + c4 * 4];
            *(__half2*)&Xh[r * PSTR + c4 * 4]     = __float22half2_rn(make_float2(v.x, v.y));
            *(__half2*)&Xh[r * PSTR + c4 * 4 + 2] = __float22half2_rn(make_float2(v.z, v.w));
        }
        // W tile 64x64 -> fp16 transposed [n][k]
        #pragma unroll
        for (int i = 0; i < 4; i++) {
            int idx = t + i * 256;
            int r = idx >> 4, c4 = idx & 15;   // r = k row, 4*c4 = n base
            float4 w = *(const float4*)&W[(size_t)(k0 + r) * HD + col0 + c4 * 4];
            Wh[(c4 * 4 + 0) * PSTR + r] = __float2half_rn(w.x);
            Wh[(c4 * 4 + 1) * PSTR + r] = __float2half_rn(w.y);
            Wh[(c4 * 4 + 2) * PSTR + r] = __float2half_rn(w.z);
            Wh[(c4 * 4 + 3) * PSTR + r] = __float2half_rn(w.w);
        }
        __syncthreads();

        #pragma unroll
        for (int kc = 0; kc < 4; kc++) {
            unsigned a[2][4];
            #pragma unroll
            for (int i = 0; i < 2; i++) {
                const __half* ar = &Xh[(warp_m + 16 * i + g) * PSTR + kc * 16];
                a[i][0] = *(const unsigned*)&ar[2 * q];
                a[i][1] = *(const unsigned*)&ar[PSTR * 8 + 2 * q];
                a[i][2] = *(const unsigned*)&ar[8 + 2 * q];
                a[i][3] = *(const unsigned*)&ar[PSTR * 8 + 8 + 2 * q];
            }
            #pragma unroll
            for (int j = 0; j < 4; j++) {
                const unsigned* br = (const unsigned*)&Wh[(warp_n + 8 * j + g) * PSTR + kc * 16];
                unsigned b0 = br[q];
                unsigned b1 = br[4 + q];
                #pragma unroll
                for (int i = 0; i < 2; i++)
                    mma_f16(acc[i][j], a[i][0], a[i][1], a[i][2], a[i][3], b0, b1);
            }
        }
        __syncthreads();
    }

    // stage fp32 result (overlays Xh/Wh — all reads done)
    #pragma unroll
    for (int i = 0; i < 2; i++)
        #pragma unroll
        for (int j = 0; j < 4; j++) {
            float* sr = &Stage[(warp_m + 16 * i + g) * PSTR + warp_n + 8 * j + 2 * q];
            sr[0] = acc[i][j][0];
            sr[1] = acc[i][j][1];
            sr[PSTR * 8] = acc[i][j][2];
            sr[PSTR * 8 + 1] = acc[i][j][3];
        }
    __syncthreads();

    // bias + fp16 row-major write; keep biased fp32 in Stage for transpose pass
    #pragma unroll
    for (int i = 0; i < 8; i++) {
        int idx = t + i * 256;
        int r = idx >> 4, c4 = idx & 15;
        float4 v = *(float4*)&Stage[r * PSTR + c4 * 4];
        float4 bb = *(const float4*)&bias[col0 + c4 * 4];
        v.x += bb.x; v.y += bb.y; v.z += bb.z; v.w += bb.w;
        *(float4*)&Stage[r * PSTR + c4 * 4] = v;
        __half2 p0 = __float22half2_rn(make_float2(v.x, v.y));
        __half2 p1 = __float22half2_rn(make_float2(v.z, v.w));
        *(__half2*)&g_hh[(size_t)(row0 + r) * HD + col0 + c4 * 4] = p0;
        *(__half2*)&g_hh[(size_t)(row0 + r) * HD + col0 + c4 * 4 + 2] = p1;
    }
    __syncthreads();

    // transposed fp16 write: g_hhT[b][hh][d][n], n-range 128
    const int b = row0 >> 11;
    const int n0 = row0 & (NN - 1);
    const int hh = col0 >> 6;
    #pragma unroll
    for (int i = 0; i < 8; i++) {
        int idx = t + i * 256;
        int dr = idx >> 5, nc = idx & 31;
        __half2 p0 = __float22half2_rn(make_float2(Stage[(nc * 4 + 0) * PSTR + dr],
                                                   Stage[(nc * 4 + 1) * PSTR + dr]));
        __half2 p1 = __float22half2_rn(make_float2(Stage[(nc * 4 + 2) * PSTR + dr],
                                                   Stage[(nc * 4 + 3) * PSTR + dr]));
        __half* dst = &g_hhT[((size_t)(b * HH + hh) * DD + dr) * NN + n0 + nc * 4];
        *(__half2*)&dst[0] = p0;
        *(__half2*)&dst[2] = p1;
    }
}

// ---------------------------------------------------------------------------
// K2: fused attention (mma.m16n8k16 fp16, fp32 accum), software-pipelined:
// per iter:  exp_it -> S_{it+1} (tensor) -> AV_it (tensor); 3-slot cp.async ring.
// CTA: 256 threads / 8 warps; 128-row q-tile; 2 CTAs/SM.
// ---------------------------------------------------------------------------
#define STRH 72                 // smem tile stride (halfs)
#define TILEH (64 * STRH)       // halfs per tile
#define SLOTH (2 * TILEH)       // K+V per slot
#define FSMEM (3 * SLOTH * 2)   // bytes: 55296

__global__ __launch_bounds__(256, 2) void k_fused() {
    extern __shared__ __half sm[];

    const int t = threadIdx.x;
    const int lane = t & 31;
    const int wid = t >> 5;
    const int g = lane >> 2;
    const int q = lane & 3;
    const int row0 = blockIdx.x * 128;
    const int bh = blockIdx.y;
    const int b = bh >> 3, hh = bh & 7;

    const __half* Hb = g_hh + (size_t)b * NN * HD + hh * DD;
    const __half* HTb = g_hhT + (size_t)bh * DD * NN;
    const int r_lo = row0 + wid * 16 + g;
    const int r_hi = r_lo + 8;

    // prefetch tiles 0,1 into slots 0,1
    #pragma unroll
    for (int tile = 0; tile < 2; tile++) {
        __half* kb = sm + tile * SLOTH;
        __half* vb = kb + TILEH;
        #pragma unroll
        for (int k = 0; k < 2; k++) {
            int c = t + k * 256;
            int r = c >> 3, seg = c & 7;
            unsigned dk = (unsigned)__cvta_generic_to_shared(&kb[r * STRH + seg * 8]);
            asm volatile("cp.async.ca.shared.global [%0], [%1], 16;"
                         :: "r"(dk), "l"(&Hb[(size_t)(tile * 64 + r) * HD + seg * 8]));
            unsigned dv = (unsigned)__cvta_generic_to_shared(&vb[r * STRH + seg * 8]);
            asm volatile("cp.async.ca.shared.global [%0], [%1], 16;"
                         :: "r"(dv), "l"(&HTb[(size_t)r * NN + tile * 64 + seg * 8]));
        }
        asm volatile("cp.async.commit_group;");
    }

    // Q fragments fp16 (half2 pairs)
    unsigned Qa[4][4];
    #pragma unroll
    for (int kc = 0; kc < 4; kc++) {
        Qa[kc][0] = *(const unsigned*)&Hb[(size_t)r_lo * HD + 16 * kc + 2 * q];
        Qa[kc][1] = *(const unsigned*)&Hb[(size_t)r_hi * HD + 16 * kc + 2 * q];
        Qa[kc][2] = *(const unsigned*)&Hb[(size_t)r_lo * HD + 16 * kc + 8 + 2 * q];
        Qa[kc][3] = *(const unsigned*)&Hb[(size_t)r_hi * HD + 16 * kc + 8 + 2 * q];
    }

    float Oa[8][4];
    #pragma unroll
    for (int f = 0; f < 8; f++)
        #pragma unroll
        for (int e = 0; e < 4; e++) Oa[f][e] = 0.f;
    float rs_lo = 0.f, rs_hi = 0.f;

    const unsigned* mrow_lo = &g_mask[((size_t)b * NN + r_lo) * NW];
    const unsigned* mrow_hi = &g_mask[((size_t)b * NN + r_hi) * NW];
    __half* Srow_lo = &g_S[((size_t)bh * NN + r_lo) * NN];
    __half* Srow_hi = &g_S[((size_t)bh * NN + r_hi) * NN];

    // wait tile 0, compute S_0
    asm volatile("cp.async.wait_group 1;");
    __syncthreads();

    float Sa[8][4];
    #pragma unroll
    for (int f = 0; f < 8; f++)
        #pragma unroll
        for (int e = 0; e < 4; e++) Sa[f][e] = 0.f;
    {
        const __half* Kb = sm;   // slot 0
        #pragma unroll
        for (int f = 0; f < 8; f++) {
            const unsigned* kr = (const unsigned*)&Kb[(8 * f + g) * STRH];
            #pragma unroll
            for (int kc = 0; kc < 4; kc++)
                mma_f16(Sa[f], Qa[kc][0], Qa[kc][1], Qa[kc][2], Qa[kc][3],
                        kr[8 * kc + q], kr[8 * kc + 4 + q]);
        }
    }

    for (int it = 0; it < 32; it++) {
        const int m0 = it * 64;

        // ---- exp phase: Sa -> H (half2), rowsum, stream E ----
        const unsigned m00 = __ldg(&mrow_lo[it * 2]);
        const unsigned m01 = __ldg(&mrow_lo[it * 2 + 1]);
        const unsigned m10 = __ldg(&mrow_hi[it * 2]);
        const unsigned m11 = __ldg(&mrow_hi[it * 2 + 1]);

        unsigned H01[8], H23[8];
        #pragma unroll
        for (int f = 0; f < 8; f++) {
            const unsigned wlo = (f < 4) ? m00 : m01;
            const unsigned whi = (f < 4) ? m10 : m11;
            const int sh = (8 * f + 2 * q) & 31;
            float e0 = ((wlo >> sh) & 1u)       ? __expf(fmaf(Sa[f][0], SCALE, -BIAS14)) : 0.f;
            float e1 = ((wlo >> (sh + 1)) & 1u) ? __expf(fmaf(Sa[f][1], SCALE, -BIAS14)) : 0.f;
            float e2 = ((whi >> sh) & 1u)       ? __expf(fmaf(Sa[f][2], SCALE, -BIAS14)) : 0.f;
            float e3 = ((whi >> (sh + 1)) & 1u) ? __expf(fmaf(Sa[f][3], SCALE, -BIAS14)) : 0.f;
            rs_lo += e0 + e1;
            rs_hi += e2 + e3;
            __half2 p01 = __float22half2_rn(make_float2(e0, e1));
            __half2 p23 = __float22half2_rn(make_float2(e2, e3));
            H01[f] = *(unsigned*)&p01;
            H23[f] = *(unsigned*)&p23;
            __stcs((__half2*)&Srow_lo[m0 + 8 * f + 2 * q], p01);
            __stcs((__half2*)&Srow_hi[m0 + 8 * f + 2 * q], p23);
        }

        if (it < 31) {
            __syncthreads();   // all warps done with slot (it-1); tile it+1 about to be used

            if (it < 30) {
                const int tile = it + 2;
                __half* kb = sm + (tile % 3) * SLOTH;
                __half* vb = kb + TILEH;
                #pragma unroll
                for (int k = 0; k < 2; k++) {
                    int c = t + k * 256;
                    int r = c >> 3, seg = c & 7;
                    unsigned dk = (unsigned)__cvta_generic_to_shared(&kb[r * STRH + seg * 8]);
                    asm volatile("cp.async.ca.shared.global [%0], [%1], 16;"
                                 :: "r"(dk), "l"(&Hb[(size_t)(tile * 64 + r) * HD + seg * 8]));
                    unsigned dv = (unsigned)__cvta_generic_to_shared(&vb[r * STRH + seg * 8]);
                    asm volatile("cp.async.ca.shared.global [%0], [%1], 16;"
                                 :: "r"(dv), "l"(&HTb[(size_t)r * NN + tile * 64 + seg * 8]));
                }
                asm volatile("cp.async.commit_group;");
                asm volatile("cp.async.wait_group 1;");
            } else {
                asm volatile("cp.async.wait_group 0;");
            }

            // ---- S_{it+1} (tensor; overlaps exp latency) ----
            const __half* Kb = sm + ((it + 1) % 3) * SLOTH;
            #pragma unroll
            for (int f = 0; f < 8; f++)
                #pragma unroll
                for (int e = 0; e < 4; e++) Sa[f][e] = 0.f;
            #pragma unroll
            for (int f = 0; f < 8; f++) {
                const unsigned* kr = (const unsigned*)&Kb[(8 * f + g) * STRH];
                #pragma unroll
                for (int kc = 0; kc < 4; kc++)
                    mma_f16(Sa[f], Qa[kc][0], Qa[kc][1], Qa[kc][2], Qa[kc][3],
                            kr[8 * kc + q], kr[8 * kc + 4 + q]);
            }
        }

        // ---- AV_it: O += E V ----
        const __half* Vb = sm + (it % 3) * SLOTH + TILEH;
        #pragma unroll
        for (int df = 0; df < 8; df++) {
            const unsigned* vr = (const unsigned*)&Vb[(8 * df + g) * STRH];
            #pragma unroll
            for (int kk = 0; kk < 4; kk++)
                mma_f16(Oa[df], H01[2 * kk], H23[2 * kk], H01[2 * kk + 1], H23[2 * kk + 1],
                        vr[8 * kk + q], vr[8 * kk + 4 + q]);
        }
    }

    // ---- epilogue ----
    rs_lo += __shfl_xor_sync(0xffffffffu, rs_lo, 1);
    rs_lo += __shfl_xor_sync(0xffffffffu, rs_lo, 2);
    rs_hi += __shfl_xor_sync(0xffffffffu, rs_hi, 1);
    rs_hi += __shfl_xor_sync(0xffffffffu, rs_hi, 2);
    if (q == 0) {
        g_rowsum[(size_t)bh * NN + r_lo] = rs_lo;
        g_rowsum[(size_t)bh * NN + r_hi] = rs_hi;
    }
    const float inv_lo = 1.f / rs_lo;
    const float inv_hi = 1.f / rs_hi;
    float* O_lo = &g_O[((size_t)b * NN + r_lo) * HD + hh * DD];
    float* O_hi = &g_O[((size_t)b * NN + r_hi) * HD + hh * DD];
    #pragma unroll
    for (int df = 0; df < 8; df++) {
        *(float2*)&O_lo[8 * df + 2 * q] = make_float2(Oa[df][0] * inv_lo, Oa[df][1] * inv_lo);
        *(float2*)&O_hi[8 * df + 2 * q] = make_float2(Oa[df][2] * inv_hi, Oa[df][3] * inv_hi);
    }
}

// ---------------------------------------------------------------------------
// K3: LayerNorm (out head) + mean over heads (out tail), one block per row
// ---------------------------------------------------------------------------
__global__ void k_epi(const float* __restrict__ gamma, const float* __restrict__ beta,
                      float* __restrict__ out, float* __restrict__ out_mean) {
    __shared__ float red[256];
    __shared__ float red2[256];
    __shared__ float inv[HH];

    const int row = blockIdx.x;
    const int b = row >> 11;
    const int n = row & (NN - 1);
    const int t = threadIdx.x;

    if (t < HH) inv[t] = 0.125f / g_rowsum[(size_t)(b * HH + t) * NN + n];

    // ---- LayerNorm: each thread owns cols t, t+256 ----
    const float* v = g_O + (size_t)row * HD;
    float v0 = v[t], v1 = v[t + 256];
    red[t] = v0 + v1;
    red2[t] = v0 * v0 + v1 * v1;
    __syncthreads();
    for (int st = 128; st > 0; st >>= 1) {
        if (t < st) { red[t] += red[t + st]; red2[t] += red2[t + st]; }
        __syncthreads();
    }
    const float mu = red[0] * (1.f / HD);
    const float var = red2[0] * (1.f / HD) - mu * mu;
    const float rstd = rsqrtf(var + EPS);

    float* orow = out + (size_t)row * HD;
    orow[t] = (v0 - mu) * rstd * gamma[t] + beta[t];
    orow[t + 256] = (v1 - mu) * rstd * gamma[t + 256] + beta[t + 256];

    // ---- mean over heads: thread t owns cols [8t, 8t+8) ----
    float acc[8];
    #pragma unroll
    for (int i = 0; i < 8; i++) acc[i] = 0.f;

    #pragma unroll
    for (int h = 0; h < HH; h++) {
        const float4 raw = __ldcs((const float4*)&g_S[((size_t)(b * HH + h) * NN + n) * NN + t * 8]);
        const __half2* hp = (const __half2*)&raw;
        const float iv = inv[h];
        #pragma unroll
        for (int j = 0; j < 4; j++) {
            float2 p = __half22float2(hp[j]);
            acc[2 * j]     += p.x * iv;
            acc[2 * j + 1] += p.y * iv;
        }
    }

    float* mrow = out_mean + (size_t)row * NN + t * 8;
    *(float4*)&mrow[0] = make_float4(acc[0], acc[1], acc[2], acc[3]);
    *(float4*)&mrow[4] = make_float4(acc[4], acc[5], acc[6], acc[7]);
}

// ---------------------------------------------------------------------------
extern "C" void kernel_launch(void* const* d_in, const int* in_sizes, int n_in,
                              void* d_out, int out_size) {
    const float* x     = (const float*)d_in[0];
    const int*   adj   = (const int*)d_in[1];
    const float* W_w   = (const float*)d_in[2];
    const float* W_b   = (const float*)d_in[3];
    const float* gamma = (const float*)d_in[4];
    const float* beta  = (const float*)d_in[5];
    float* out = (float*)d_out;
    float* out_mean = out + (size_t)BB * NN * HD;

    cudaFuncSetAttribute(k_fused, cudaFuncAttributeMaxDynamicSharedMemorySize, FSMEM);

    k_proj<<<dim3(HD / 64, (BB * NN) / 128, 2), 256>>>(x, W_w, W_b, adj);
    k_fused<<<dim3(NN / 128, BB * HH), 256, FSMEM>>>();
    k_epi<<<BB * NN, 256>>>(gamma, beta, out, out_mean);
}